// round 6
// baseline (speedup 1.0000x reference)
#include <cuda_runtime.h>
#include <math.h>

// Problem constants
#define VOCAB 50000
#define EMB   300
#define HID   256
#define BATCH 128
#define T_H   32
#define T_B   512

// -------- scratch (static device allocations; no cudaMalloc anywhere) --------
__device__ float g_XG_h[(size_t)BATCH * T_H * 768];   // headline x-projections [B*T, 768] (gates 512 | cand 256)
__device__ float g_XG_b[(size_t)BATCH * T_B * 768];   // body x-projections
__device__ float g_out_h[(size_t)BATCH * T_H * HID];  // headline layer-0 outputs
__device__ float g_out_b[(size_t)BATCH * T_B * HID];  // body layer-0 outputs
__device__ float g_hcat [(size_t)BATCH * 512];        // [h_head | h_body] final states

// ============================================================================
// Generic SGEMM: C[M,N] = A[M,K] @ B[K,N] + bias,  row-major.
// GATHER: A row r = emb[ids[r]] (embedding gather fused into the A-tile load).
// BM=128, BN=64, BK=8, 256 threads, 8x4 micro-tile per thread.
// ============================================================================
template <bool GATHER>
__global__ __launch_bounds__(256)
void sgemm_kernel(const float* __restrict__ A, const int* __restrict__ ids, int lda,
                  const float* __restrict__ Bm, int ldb,
                  const float* __restrict__ bias,
                  float* __restrict__ C, int ldc, int coff,
                  int M, int N, int K)
{
    const int BM = 128, BN = 64, BK = 8;
    __shared__ float As[BK][BM];
    __shared__ float Bs[BK][BN];

    int nbn = N / BN;
    int bm = blockIdx.x / nbn;
    int bn = blockIdx.x % nbn;
    int tid = threadIdx.x;
    int tx = tid & 15;        // 0..15 -> 4 cols each
    int ty = tid >> 4;        // 0..15 -> 8 rows each

    float acc[8][4];
#pragma unroll
    for (int i = 0; i < 8; i++)
#pragma unroll
        for (int j = 0; j < 4; j++) acc[i][j] = 0.0f;

    // A-tile loader mapping: thread -> (row ar, 4 consecutive k at ak)
    int ar = tid >> 1;            // 0..127
    int ak = (tid & 1) * 4;       // 0 or 4
    int arow = bm * BM + ar;
    const float* arow_ptr;
    if (GATHER) arow_ptr = A + (size_t)ids[arow] * lda;
    else        arow_ptr = A + (size_t)arow * lda;

    // B-tile loader mapping: thread -> (k-row bk, 2 consecutive cols bc)
    int bkr = tid >> 5;           // 0..7
    int bc  = (tid & 31) * 2;     // 0..62
    const float* bptr = Bm + (size_t)bn * BN + bc;

    for (int k0 = 0; k0 < K; k0 += BK) {
        float4 av = make_float4(0.f, 0.f, 0.f, 0.f);
        if (k0 + ak < K) av = *(const float4*)(arow_ptr + k0 + ak);
        float2 bv = make_float2(0.f, 0.f);
        if (k0 + bkr < K) bv = *(const float2*)(bptr + (size_t)(k0 + bkr) * ldb);

        __syncthreads();
        As[ak + 0][ar] = av.x; As[ak + 1][ar] = av.y;
        As[ak + 2][ar] = av.z; As[ak + 3][ar] = av.w;
        Bs[bkr][bc] = bv.x; Bs[bkr][bc + 1] = bv.y;
        __syncthreads();

#pragma unroll
        for (int kk = 0; kk < BK; kk++) {
            float4 b4 = *(const float4*)&Bs[kk][tx * 4];
            float4 a0 = *(const float4*)&As[kk][ty * 8];
            float4 a1 = *(const float4*)&As[kk][ty * 8 + 4];
            float arr[8] = {a0.x, a0.y, a0.z, a0.w, a1.x, a1.y, a1.z, a1.w};
            float brr[4] = {b4.x, b4.y, b4.z, b4.w};
#pragma unroll
            for (int i = 0; i < 8; i++)
#pragma unroll
                for (int j = 0; j < 4; j++)
                    acc[i][j] += arr[i] * brr[j];
        }
    }

    float4 bb = *(const float4*)&bias[bn * BN + tx * 4];
    float bbr[4] = {bb.x, bb.y, bb.z, bb.w};
#pragma unroll
    for (int i = 0; i < 8; i++) {
        int row = bm * BM + ty * 8 + i;
        float4 o;
        o.x = acc[i][0] + bbr[0];
        o.y = acc[i][1] + bbr[1];
        o.z = acc[i][2] + bbr[2];
        o.w = acc[i][3] + bbr[3];
        *(float4*)(C + (size_t)row * ldc + coff + bn * BN + tx * 4) = o;
    }
}

// ============================================================================
// GRU recurrent scan. One block = 2 batch rows, 256 threads.
// Weights (h-part) read straight from the input matrices (k-major), lanes own
// adjacent columns -> fully coalesced LDG; h / r / u / r*h live in smem.
// Grid = 128 blocks: [0,64) = body stream, [64,128) = headline stream.
// ============================================================================
struct ScanArgs {
    const float* XG;    // [B*T, 768] x-projections (gates 0..511, cand 512..767)
    const float* Wgh;   // [256, 512] h-part of gate weights (k-major)
    const float* Wch;   // [256, 256] h-part of cand weights (k-major)
    const int*   ids;   // [B, T]
    float*       outs;  // [B*T, 256] or nullptr
    float*       hfin;  // g_hcat or nullptr
    int          hoff;  // column offset into g_hcat
    int          T;
};

__global__ __launch_bounds__(256)
void gru_scan_kernel(ScanArgs body, ScanArgs head)
{
    ScanArgs A = (blockIdx.x < 64) ? body : head;
    int bid = blockIdx.x & 63;
    int b0 = bid * 2;
    int b1 = b0 + 1;
    int tid = threadIdx.x;

    __shared__ float sh_h[2][HID];
    __shared__ float sh_ru[2][2 * HID];
    __shared__ float sh_rh[2][HID];

    sh_h[0][tid] = 0.0f;
    sh_h[1][tid] = 0.0f;
    __syncthreads();

    const int T = A.T;
    const int c0 = tid * 2;
    const float* __restrict__ Wgh = A.Wgh;
    const float* __restrict__ Wch = A.Wch;

    for (int t = 0; t < T; t++) {
        size_t xg0 = ((size_t)(b0 * T + t)) * 768;
        size_t xg1 = ((size_t)(b1 * T + t)) * 768;

        // ---- gates: ru = sigmoid(x-part + h @ Wgh) ----
        float2 x0 = *(const float2*)(A.XG + xg0 + c0);
        float2 x1 = *(const float2*)(A.XG + xg1 + c0);
        float a00 = x0.x, a01 = x0.y, a10 = x1.x, a11 = x1.y;
#pragma unroll 8
        for (int k = 0; k < HID; k++) {
            float2 w = *(const float2*)(Wgh + (size_t)k * 512 + c0);
            float h0 = sh_h[0][k];
            float h1 = sh_h[1][k];
            a00 += w.x * h0; a01 += w.y * h0;
            a10 += w.x * h1; a11 += w.y * h1;
        }
        sh_ru[0][c0]     = 1.0f / (1.0f + expf(-a00));
        sh_ru[0][c0 + 1] = 1.0f / (1.0f + expf(-a01));
        sh_ru[1][c0]     = 1.0f / (1.0f + expf(-a10));
        sh_ru[1][c0 + 1] = 1.0f / (1.0f + expf(-a11));
        __syncthreads();

        // ---- r * h ----
        sh_rh[0][tid] = sh_ru[0][tid] * sh_h[0][tid];
        sh_rh[1][tid] = sh_ru[1][tid] * sh_h[1][tid];
        __syncthreads();

        // ---- candidate: c = tanh(x-part + (r*h) @ Wch) ----
        float cacc0 = A.XG[xg0 + 512 + tid];
        float cacc1 = A.XG[xg1 + 512 + tid];
#pragma unroll 8
        for (int k = 0; k < HID; k++) {
            float w = Wch[(size_t)k * 256 + tid];
            cacc0 += w * sh_rh[0][k];
            cacc1 += w * sh_rh[1][k];
        }
        float cc0 = tanhf(cacc0);
        float cc1 = tanhf(cacc1);

        // ---- update ----
        float u0 = sh_ru[0][256 + tid];
        float u1 = sh_ru[1][256 + tid];
        float h0o = sh_h[0][tid];
        float h1o = sh_h[1][tid];
        float hn0 = u0 * h0o + (1.0f - u0) * cc0;
        float hn1 = u1 * h1o + (1.0f - u1) * cc1;
        bool v0 = (A.ids[b0 * T + t] != 0);
        bool v1 = (A.ids[b1 * T + t] != 0);
        if (A.outs) {
            A.outs[((size_t)(b0 * T + t)) * 256 + tid] = v0 ? hn0 : 0.0f;
            A.outs[((size_t)(b1 * T + t)) * 256 + tid] = v1 ? hn1 : 0.0f;
        }
        sh_h[0][tid] = v0 ? hn0 : h0o;
        sh_h[1][tid] = v1 ? hn1 : h1o;
        __syncthreads();
    }

    if (A.hfin) {
        A.hfin[(size_t)b0 * 512 + A.hoff + tid] = sh_h[0][tid];
        A.hfin[(size_t)b1 * 512 + A.hoff + tid] = sh_h[1][tid];
    }
}

// ============================================================================
// Final projection: out[128,4] = [h_head | h_body] @ W_pred + b_pred
// ============================================================================
__global__ void final_pred_kernel(const float* __restrict__ Wp,
                                  const float* __restrict__ bp,
                                  float* __restrict__ out)
{
    int b = threadIdx.x;   // 0..127
    float a0 = bp[0], a1 = bp[1], a2 = bp[2], a3 = bp[3];
    const float* h = g_hcat + (size_t)b * 512;
#pragma unroll 8
    for (int j = 0; j < 512; j++) {
        float hv = h[j];
        float4 w = *(const float4*)(Wp + j * 4);
        a0 += hv * w.x; a1 += hv * w.y; a2 += hv * w.z; a3 += hv * w.w;
    }
    *(float4*)(out + b * 4) = make_float4(a0, a1, a2, a3);
}

// ============================================================================
// Launch: L0 x-GEMMs -> L0 scan -> L1 x-GEMMs -> L1 scan -> final projection
// ============================================================================
extern "C" void kernel_launch(void* const* d_in, const int* in_sizes, int n_in,
                              void* d_out, int out_size)
{
    (void)n_in; (void)out_size;

    // Fixed slots (same in both plausible metadata orders)
    const int*   ids_h  = (const int*)d_in[0];
    const int*   ids_b  = (const int*)d_in[1];
    const float* emb    = (const float*)d_in[2];

    // Detect metadata layout from element counts.
    // Dict order (setup_inputs insertion): [3]=W_pred(2048), [4]=b_pred(4),
    //   [5..8]=hd0, [9..12]=hd1, [13..16]=bd0, [17..20]=bd1.
    // Signature order: [3..6]=hd0, [7..10]=hd1, [11..14]=bd0, [15..18]=bd1,
    //   [19]=W_pred, [20]=b_pred.
    const float *hd0_Wg, *hd0_bg, *hd0_Wc, *hd0_bc;
    const float *hd1_Wg, *hd1_bg, *hd1_Wc, *hd1_bc;
    const float *bd0_Wg, *bd0_bg, *bd0_Wc, *bd0_bc;
    const float *bd1_Wg, *bd1_bg, *bd1_Wc, *bd1_bc;
    const float *W_pred, *b_pred;

    if (in_sizes[3] == (2 * HID) * 4 && in_sizes[4] == 4) {
        // dict order
        W_pred = (const float*)d_in[3];
        b_pred = (const float*)d_in[4];
        hd0_Wg = (const float*)d_in[5];  hd0_bg = (const float*)d_in[6];
        hd0_Wc = (const float*)d_in[7];  hd0_bc = (const float*)d_in[8];
        hd1_Wg = (const float*)d_in[9];  hd1_bg = (const float*)d_in[10];
        hd1_Wc = (const float*)d_in[11]; hd1_bc = (const float*)d_in[12];
        bd0_Wg = (const float*)d_in[13]; bd0_bg = (const float*)d_in[14];
        bd0_Wc = (const float*)d_in[15]; bd0_bc = (const float*)d_in[16];
        bd1_Wg = (const float*)d_in[17]; bd1_bg = (const float*)d_in[18];
        bd1_Wc = (const float*)d_in[19]; bd1_bc = (const float*)d_in[20];
    } else {
        // signature order
        hd0_Wg = (const float*)d_in[3];  hd0_bg = (const float*)d_in[4];
        hd0_Wc = (const float*)d_in[5];  hd0_bc = (const float*)d_in[6];
        hd1_Wg = (const float*)d_in[7];  hd1_bg = (const float*)d_in[8];
        hd1_Wc = (const float*)d_in[9];  hd1_bc = (const float*)d_in[10];
        bd0_Wg = (const float*)d_in[11]; bd0_bg = (const float*)d_in[12];
        bd0_Wc = (const float*)d_in[13]; bd0_bc = (const float*)d_in[14];
        bd1_Wg = (const float*)d_in[15]; bd1_bg = (const float*)d_in[16];
        bd1_Wc = (const float*)d_in[17]; bd1_bc = (const float*)d_in[18];
        W_pred = (const float*)d_in[19];
        b_pred = (const float*)d_in[20];
    }

    float* out = (float*)d_out;

    float *XG_h, *XG_b, *out_h, *out_b, *hcat;
    cudaGetSymbolAddress((void**)&XG_h, g_XG_h);
    cudaGetSymbolAddress((void**)&XG_b, g_XG_b);
    cudaGetSymbolAddress((void**)&out_h, g_out_h);
    cudaGetSymbolAddress((void**)&out_b, g_out_b);
    cudaGetSymbolAddress((void**)&hcat, g_hcat);

    const int Mh = BATCH * T_H;   // 4096
    const int Mb = BATCH * T_B;   // 65536

    // ---- Layer-0 x-projections (embedding gather fused) ----
    sgemm_kernel<true><<<(Mh / 128) * (512 / 64), 256>>>(
        emb, ids_h, EMB, hd0_Wg, 512, hd0_bg, XG_h, 768, 0,   Mh, 512, EMB);
    sgemm_kernel<true><<<(Mh / 128) * (256 / 64), 256>>>(
        emb, ids_h, EMB, hd0_Wc, 256, hd0_bc, XG_h, 768, 512, Mh, 256, EMB);
    sgemm_kernel<true><<<(Mb / 128) * (512 / 64), 256>>>(
        emb, ids_b, EMB, bd0_Wg, 512, bd0_bg, XG_b, 768, 0,   Mb, 512, EMB);
    sgemm_kernel<true><<<(Mb / 128) * (256 / 64), 256>>>(
        emb, ids_b, EMB, bd0_Wc, 256, bd0_bc, XG_b, 768, 512, Mb, 256, EMB);

    // ---- Layer-0 scan (body + headline in one launch) ----
    {
        ScanArgs body = { XG_b, bd0_Wg + (size_t)EMB * 512, bd0_Wc + (size_t)EMB * 256,
                          ids_b, out_b, nullptr, 0, T_B };
        ScanArgs head = { XG_h, hd0_Wg + (size_t)EMB * 512, hd0_Wc + (size_t)EMB * 256,
                          ids_h, out_h, nullptr, 0, T_H };
        gru_scan_kernel<<<128, 256>>>(body, head);
    }

    // ---- Layer-1 x-projections (reuse XG buffers) ----
    sgemm_kernel<false><<<(Mh / 128) * (512 / 64), 256>>>(
        out_h, nullptr, HID, hd1_Wg, 512, hd1_bg, XG_h, 768, 0,   Mh, 512, HID);
    sgemm_kernel<false><<<(Mh / 128) * (256 / 64), 256>>>(
        out_h, nullptr, HID, hd1_Wc, 256, hd1_bc, XG_h, 768, 512, Mh, 256, HID);
    sgemm_kernel<false><<<(Mb / 128) * (512 / 64), 256>>>(
        out_b, nullptr, HID, bd1_Wg, 512, bd1_bg, XG_b, 768, 0,   Mb, 512, HID);
    sgemm_kernel<false><<<(Mb / 128) * (256 / 64), 256>>>(
        out_b, nullptr, HID, bd1_Wc, 256, bd1_bc, XG_b, 768, 512, Mb, 256, HID);

    // ---- Layer-1 scan -> final hidden states ----
    {
        ScanArgs body = { XG_b, bd1_Wg + (size_t)HID * 512, bd1_Wc + (size_t)HID * 256,
                          ids_b, nullptr, hcat, 256, T_B };
        ScanArgs head = { XG_h, hd1_Wg + (size_t)HID * 512, hd1_Wc + (size_t)HID * 256,
                          ids_h, nullptr, hcat, 0, T_H };
        gru_scan_kernel<<<128, 256>>>(body, head);
    }

    // ---- Final projection ----
    final_pred_kernel<<<1, 128>>>(W_pred, b_pred, out);
}

// round 8
// speedup vs baseline: 1.6716x; 1.6716x over previous
#include <cuda_runtime.h>
#include <math.h>

// Problem constants
#define VOCAB 50000
#define EMB   300
#define HID   256
#define BATCH 128
#define T_H   32
#define T_B   512

// -------- scratch (static device allocations; no cudaMalloc anywhere) --------
__device__ float g_XG_h[(size_t)BATCH * T_H * 768];   // headline x-projections [B*T, 768] (gates 512 | cand 256)
__device__ float g_XG_b[(size_t)BATCH * T_B * 768];   // body x-projections
__device__ float g_out_h[(size_t)BATCH * T_H * HID];  // headline layer-0 outputs
__device__ float g_out_b[(size_t)BATCH * T_B * HID];  // body layer-0 outputs
__device__ float g_hcat [(size_t)BATCH * 512];        // [h_head | h_body] final states

// ============================================================================
// Generic SGEMM: C[M,N] = A[M,K] @ B[K,N] + bias,  row-major.
// GATHER: A row r = emb[ids[r]] (embedding gather fused into the A-tile load).
// BM=128, BN=64, BK=8, 256 threads, 8x4 micro-tile per thread.
// ============================================================================
template <bool GATHER>
__global__ __launch_bounds__(256)
void sgemm_kernel(const float* __restrict__ A, const int* __restrict__ ids, int lda,
                  const float* __restrict__ Bm, int ldb,
                  const float* __restrict__ bias,
                  float* __restrict__ C, int ldc, int coff,
                  int M, int N, int K)
{
    const int BM = 128, BN = 64, BK = 8;
    __shared__ float As[BK][BM];
    __shared__ float Bs[BK][BN];

    int nbn = N / BN;
    int bm = blockIdx.x / nbn;
    int bn = blockIdx.x % nbn;
    int tid = threadIdx.x;
    int tx = tid & 15;        // 0..15 -> 4 cols each
    int ty = tid >> 4;        // 0..15 -> 8 rows each

    float acc[8][4];
#pragma unroll
    for (int i = 0; i < 8; i++)
#pragma unroll
        for (int j = 0; j < 4; j++) acc[i][j] = 0.0f;

    // A-tile loader mapping: thread -> (row ar, 4 consecutive k at ak)
    int ar = tid >> 1;            // 0..127
    int ak = (tid & 1) * 4;       // 0 or 4
    int arow = bm * BM + ar;
    const float* arow_ptr;
    if (GATHER) arow_ptr = A + (size_t)ids[arow] * lda;
    else        arow_ptr = A + (size_t)arow * lda;

    // B-tile loader mapping: thread -> (k-row bk, 2 consecutive cols bc)
    int bkr = tid >> 5;           // 0..7
    int bc  = (tid & 31) * 2;     // 0..62
    const float* bptr = Bm + (size_t)bn * BN + bc;

    for (int k0 = 0; k0 < K; k0 += BK) {
        float4 av = make_float4(0.f, 0.f, 0.f, 0.f);
        if (k0 + ak < K) av = *(const float4*)(arow_ptr + k0 + ak);
        float2 bv = make_float2(0.f, 0.f);
        if (k0 + bkr < K) bv = *(const float2*)(bptr + (size_t)(k0 + bkr) * ldb);

        __syncthreads();
        As[ak + 0][ar] = av.x; As[ak + 1][ar] = av.y;
        As[ak + 2][ar] = av.z; As[ak + 3][ar] = av.w;
        Bs[bkr][bc] = bv.x; Bs[bkr][bc + 1] = bv.y;
        __syncthreads();

#pragma unroll
        for (int kk = 0; kk < BK; kk++) {
            float4 b4 = *(const float4*)&Bs[kk][tx * 4];
            float4 a0 = *(const float4*)&As[kk][ty * 8];
            float4 a1 = *(const float4*)&As[kk][ty * 8 + 4];
            float arr[8] = {a0.x, a0.y, a0.z, a0.w, a1.x, a1.y, a1.z, a1.w};
            float brr[4] = {b4.x, b4.y, b4.z, b4.w};
#pragma unroll
            for (int i = 0; i < 8; i++)
#pragma unroll
                for (int j = 0; j < 4; j++)
                    acc[i][j] += arr[i] * brr[j];
        }
    }

    float4 bb = *(const float4*)&bias[bn * BN + tx * 4];
    float bbr[4] = {bb.x, bb.y, bb.z, bb.w};
#pragma unroll
    for (int i = 0; i < 8; i++) {
        int row = bm * BM + ty * 8 + i;
        float4 o;
        o.x = acc[i][0] + bbr[0];
        o.y = acc[i][1] + bbr[1];
        o.z = acc[i][2] + bbr[2];
        o.w = acc[i][3] + bbr[3];
        *(float4*)(C + (size_t)row * ldc + coff + bn * BN + tx * 4) = o;
    }
}

// ============================================================================
// GRU recurrent scan, latency-optimized.
// One block = 2 batch rows, 512 threads (16 warps) with a k-split:
//   warps 0-7  accumulate k in [0,128)
//   warps 8-15 accumulate k in [128,256)
// Partial sums are combined via smem once per step (outside the k-loops).
// Weight loads are wide coalesced LDG.64 straight from the (k-major) input
// matrices; h / r*h are stored as float2 (row0,row1) pairs in smem so each
// k-iteration needs a single broadcast LDS.64.
// Grid = 128 blocks: [0,64) = body stream, [64,128) = headline stream.
// ============================================================================
struct ScanArgs {
    const float* XG;    // [B*T, 768] x-projections (gates 0..511, cand 512..767)
    const float* Wgh;   // [256, 512] h-part of gate weights (k-major)
    const float* Wch;   // [256, 256] h-part of cand weights (k-major)
    const int*   ids;   // [B, T]
    float*       outs;  // [B*T, 256] or nullptr
    float*       hfin;  // g_hcat or nullptr
    int          hoff;  // column offset into g_hcat
    int          T;
};

__global__ __launch_bounds__(512)
void gru_scan_kernel(ScanArgs body, ScanArgs head)
{
    ScanArgs A = (blockIdx.x < 64) ? body : head;
    int bid = blockIdx.x & 63;
    int b0 = bid * 2;
    int b1 = b0 + 1;
    int tid = threadIdx.x;
    int half = tid >> 8;          // k-half: 0 or 1
    int ht   = tid & 255;         // thread-in-half
    int kbeg = half * 128;

    __shared__ float2 sh_h2 [HID];        // (h_b0[k], h_b1[k])
    __shared__ float2 sh_rh2[HID];        // (r*h pairs)
    __shared__ float2 sh_u2 [HID];        // update-gate pairs
    __shared__ float2 sh_part [2][2 * HID];  // gate partials [half][col]
    __shared__ float2 sh_cpart[2][HID];      // cand partials [half][col]

    if (tid < HID) sh_h2[tid] = make_float2(0.f, 0.f);
    __syncthreads();

    const float* __restrict__ Wgh = A.Wgh;
    const float* __restrict__ Wch = A.Wch;
    const int T = A.T;

    // per-thread fixed weight base pointers
    const float* wg_base = Wgh + (size_t)kbeg * 512 + 2 * ht;  // 2 gate cols
    const float* wc_base = Wch + (size_t)kbeg * 256 + ht;      // 1 cand col

    for (int t = 0; t < T; t++) {
        const float* xg0 = A.XG + ((size_t)(b0 * T + t)) * 768;
        const float* xg1 = A.XG + ((size_t)(b1 * T + t)) * 768;

        // --- prefetch this step's x-parts + validity (hide DRAM latency) ---
        float xv0 = xg0[tid];              // gate x-part, col = tid (0..511)
        float xv1 = xg1[tid];
        float xc0 = 0.f, xc1 = 0.f;
        if (tid < HID) {
            xc0 = xg0[512 + tid];          // cand x-part
            xc1 = xg1[512 + tid];
        }
        bool v0 = (A.ids[b0 * T + t] != 0);
        bool v1 = (A.ids[b1 * T + t] != 0);

        // --- phase 1: gate partials over this thread's k-half, cols {2ht,2ht+1} ---
        float a00 = 0.f, a01 = 0.f, a10 = 0.f, a11 = 0.f;
#pragma unroll 8
        for (int kk = 0; kk < 128; kk++) {
            float2 w  = *(const float2*)(wg_base + (size_t)kk * 512);
            float2 h2 = sh_h2[kbeg + kk];
            a00 += w.x * h2.x; a01 += w.x * h2.y;
            a10 += w.y * h2.x; a11 += w.y * h2.y;
        }
        sh_part[half][2 * ht]     = make_float2(a00, a01);
        sh_part[half][2 * ht + 1] = make_float2(a10, a11);
        __syncthreads();

        // --- phase 2: combine halves + sigmoid; col c = tid (512 cols) ---
        {
            int c = tid;
            float2 p0 = sh_part[0][c];
            float2 p1 = sh_part[1][c];
            float s0 = p0.x + p1.x + xv0;
            float s1 = p0.y + p1.y + xv1;
            float g0 = 1.f / (1.f + expf(-s0));
            float g1 = 1.f / (1.f + expf(-s1));
            if (c < HID) {                 // r gate -> r*h
                float2 h2 = sh_h2[c];
                sh_rh2[c] = make_float2(g0 * h2.x, g1 * h2.y);
            } else {                       // u gate
                sh_u2[c - HID] = make_float2(g0, g1);
            }
        }
        __syncthreads();

        // --- phase 3: cand partials over this thread's k-half, col ht ---
        float c0 = 0.f, c1 = 0.f;
#pragma unroll 8
        for (int kk = 0; kk < 128; kk++) {
            float  w  = wc_base[(size_t)kk * 256];
            float2 rh = sh_rh2[kbeg + kk];
            c0 += w * rh.x;
            c1 += w * rh.y;
        }
        sh_cpart[half][ht] = make_float2(c0, c1);
        __syncthreads();

        // --- phase 4: combine + tanh + state update (threads < 256) ---
        if (tid < HID) {
            int c = tid;
            float2 p0 = sh_cpart[0][c];
            float2 p1 = sh_cpart[1][c];
            float cc0 = tanhf(p0.x + p1.x + xc0);
            float cc1 = tanhf(p0.y + p1.y + xc1);
            float2 u2 = sh_u2[c];
            float2 ho = sh_h2[c];
            float hn0 = u2.x * ho.x + (1.f - u2.x) * cc0;
            float hn1 = u2.y * ho.y + (1.f - u2.y) * cc1;
            if (A.outs) {
                A.outs[((size_t)(b0 * T + t)) * 256 + c] = v0 ? hn0 : 0.f;
                A.outs[((size_t)(b1 * T + t)) * 256 + c] = v1 ? hn1 : 0.f;
            }
            sh_h2[c] = make_float2(v0 ? hn0 : ho.x, v1 ? hn1 : ho.y);
        }
        __syncthreads();
    }

    if (A.hfin && tid < HID) {
        float2 h2 = sh_h2[tid];
        A.hfin[(size_t)b0 * 512 + A.hoff + tid] = h2.x;
        A.hfin[(size_t)b1 * 512 + A.hoff + tid] = h2.y;
    }
}

// ============================================================================
// Final projection: out[128,4] = [h_head | h_body] @ W_pred + b_pred
// ============================================================================
__global__ void final_pred_kernel(const float* __restrict__ Wp,
                                  const float* __restrict__ bp,
                                  float* __restrict__ out)
{
    int b = threadIdx.x;   // 0..127
    float a0 = bp[0], a1 = bp[1], a2 = bp[2], a3 = bp[3];
    const float* h = g_hcat + (size_t)b * 512;
#pragma unroll 8
    for (int j = 0; j < 512; j++) {
        float hv = h[j];
        float4 w = *(const float4*)(Wp + j * 4);
        a0 += hv * w.x; a1 += hv * w.y; a2 += hv * w.z; a3 += hv * w.w;
    }
    *(float4*)(out + b * 4) = make_float4(a0, a1, a2, a3);
}

// ============================================================================
// Launch: L0 x-GEMMs -> L0 scan -> L1 x-GEMMs -> L1 scan -> final projection
// ============================================================================
extern "C" void kernel_launch(void* const* d_in, const int* in_sizes, int n_in,
                              void* d_out, int out_size)
{
    (void)n_in; (void)out_size;

    // Fixed slots (same in both plausible metadata orders)
    const int*   ids_h  = (const int*)d_in[0];
    const int*   ids_b  = (const int*)d_in[1];
    const float* emb    = (const float*)d_in[2];

    // Detect metadata layout from element counts.
    const float *hd0_Wg, *hd0_bg, *hd0_Wc, *hd0_bc;
    const float *hd1_Wg, *hd1_bg, *hd1_Wc, *hd1_bc;
    const float *bd0_Wg, *bd0_bg, *bd0_Wc, *bd0_bc;
    const float *bd1_Wg, *bd1_bg, *bd1_Wc, *bd1_bc;
    const float *W_pred, *b_pred;

    if (in_sizes[3] == (2 * HID) * 4 && in_sizes[4] == 4) {
        // dict order
        W_pred = (const float*)d_in[3];
        b_pred = (const float*)d_in[4];
        hd0_Wg = (const float*)d_in[5];  hd0_bg = (const float*)d_in[6];
        hd0_Wc = (const float*)d_in[7];  hd0_bc = (const float*)d_in[8];
        hd1_Wg = (const float*)d_in[9];  hd1_bg = (const float*)d_in[10];
        hd1_Wc = (const float*)d_in[11]; hd1_bc = (const float*)d_in[12];
        bd0_Wg = (const float*)d_in[13]; bd0_bg = (const float*)d_in[14];
        bd0_Wc = (const float*)d_in[15]; bd0_bc = (const float*)d_in[16];
        bd1_Wg = (const float*)d_in[17]; bd1_bg = (const float*)d_in[18];
        bd1_Wc = (const float*)d_in[19]; bd1_bc = (const float*)d_in[20];
    } else {
        // signature order
        hd0_Wg = (const float*)d_in[3];  hd0_bg = (const float*)d_in[4];
        hd0_Wc = (const float*)d_in[5];  hd0_bc = (const float*)d_in[6];
        hd1_Wg = (const float*)d_in[7];  hd1_bg = (const float*)d_in[8];
        hd1_Wc = (const float*)d_in[9];  hd1_bc = (const float*)d_in[10];
        bd0_Wg = (const float*)d_in[11]; bd0_bg = (const float*)d_in[12];
        bd0_Wc = (const float*)d_in[13]; bd0_bc = (const float*)d_in[14];
        bd1_Wg = (const float*)d_in[15]; bd1_bg = (const float*)d_in[16];
        bd1_Wc = (const float*)d_in[17]; bd1_bc = (const float*)d_in[18];
        W_pred = (const float*)d_in[19];
        b_pred = (const float*)d_in[20];
    }

    float* out = (float*)d_out;

    float *XG_h, *XG_b, *out_h, *out_b, *hcat;
    cudaGetSymbolAddress((void**)&XG_h, g_XG_h);
    cudaGetSymbolAddress((void**)&XG_b, g_XG_b);
    cudaGetSymbolAddress((void**)&out_h, g_out_h);
    cudaGetSymbolAddress((void**)&out_b, g_out_b);
    cudaGetSymbolAddress((void**)&hcat, g_hcat);

    const int Mh = BATCH * T_H;   // 4096
    const int Mb = BATCH * T_B;   // 65536

    // ---- Layer-0 x-projections (embedding gather fused) ----
    sgemm_kernel<true><<<(Mh / 128) * (512 / 64), 256>>>(
        emb, ids_h, EMB, hd0_Wg, 512, hd0_bg, XG_h, 768, 0,   Mh, 512, EMB);
    sgemm_kernel<true><<<(Mh / 128) * (256 / 64), 256>>>(
        emb, ids_h, EMB, hd0_Wc, 256, hd0_bc, XG_h, 768, 512, Mh, 256, EMB);
    sgemm_kernel<true><<<(Mb / 128) * (512 / 64), 256>>>(
        emb, ids_b, EMB, bd0_Wg, 512, bd0_bg, XG_b, 768, 0,   Mb, 512, EMB);
    sgemm_kernel<true><<<(Mb / 128) * (256 / 64), 256>>>(
        emb, ids_b, EMB, bd0_Wc, 256, bd0_bc, XG_b, 768, 512, Mb, 256, EMB);

    // ---- Layer-0 scan (body + headline in one launch) ----
    {
        ScanArgs body = { XG_b, bd0_Wg + (size_t)EMB * 512, bd0_Wc + (size_t)EMB * 256,
                          ids_b, out_b, nullptr, 0, T_B };
        ScanArgs head = { XG_h, hd0_Wg + (size_t)EMB * 512, hd0_Wc + (size_t)EMB * 256,
                          ids_h, out_h, nullptr, 0, T_H };
        gru_scan_kernel<<<128, 512>>>(body, head);
    }

    // ---- Layer-1 x-projections (reuse XG buffers) ----
    sgemm_kernel<false><<<(Mh / 128) * (512 / 64), 256>>>(
        out_h, nullptr, HID, hd1_Wg, 512, hd1_bg, XG_h, 768, 0,   Mh, 512, HID);
    sgemm_kernel<false><<<(Mh / 128) * (256 / 64), 256>>>(
        out_h, nullptr, HID, hd1_Wc, 256, hd1_bc, XG_h, 768, 512, Mh, 256, HID);
    sgemm_kernel<false><<<(Mb / 128) * (512 / 64), 256>>>(
        out_b, nullptr, HID, bd1_Wg, 512, bd1_bg, XG_b, 768, 0,   Mb, 512, HID);
    sgemm_kernel<false><<<(Mb / 128) * (256 / 64), 256>>>(
        out_b, nullptr, HID, bd1_Wc, 256, bd1_bc, XG_b, 768, 512, Mb, 256, HID);

    // ---- Layer-1 scan -> final hidden states ----
    {
        ScanArgs body = { XG_b, bd1_Wg + (size_t)HID * 512, bd1_Wc + (size_t)HID * 256,
                          ids_b, nullptr, hcat, 256, T_B };
        ScanArgs head = { XG_h, hd1_Wg + (size_t)HID * 512, hd1_Wc + (size_t)HID * 256,
                          ids_h, nullptr, hcat, 0, T_H };
        gru_scan_kernel<<<128, 512>>>(body, head);
    }

    // ---- Final projection ----
    final_pred_kernel<<<1, 128>>>(W_pred, b_pred, out);
}

// round 9
// speedup vs baseline: 2.2842x; 1.3665x over previous
#include <cuda_runtime.h>
#include <math.h>

// Problem constants
#define VOCAB 50000
#define EMB   300
#define HID   256
#define BATCH 128
#define T_H   32
#define T_B   512

// -------- scratch (static device allocations; no cudaMalloc anywhere) --------
__device__ float g_XG_h[(size_t)BATCH * T_H * 768];   // headline x-projections [B*T, 768] (gates 512 | cand 256)
__device__ float g_XG_b[(size_t)BATCH * T_B * 768];   // body x-projections
__device__ float g_out_h[(size_t)BATCH * T_H * HID];  // headline layer-0 outputs
__device__ float g_out_b[(size_t)BATCH * T_B * HID];  // body layer-0 outputs
__device__ float g_hcat [(size_t)BATCH * 512];        // [h_head | h_body] final states

// ---- packed f32x2 helpers (Blackwell FFMA2 path; fp32-exact) ----
__device__ __forceinline__ unsigned long long pack2(float w) {
    unsigned long long r;
    asm("mov.b64 %0, {%1, %1};" : "=l"(r) : "f"(w));
    return r;
}
__device__ __forceinline__ void fma2(unsigned long long& d,
                                     unsigned long long a, unsigned long long b) {
    asm("fma.rn.f32x2 %0, %1, %2, %0;" : "+l"(d) : "l"(a), "l"(b));
}

// ============================================================================
// Generic SGEMM: C[M,N] = A[M,K] @ B[K,N] + bias,  row-major.
// GATHER: A row r = emb[ids[r]] (embedding gather fused into the A-tile load).
// BM=128, BN=64, BK=8, 256 threads, 8x4 micro-tile per thread.
// ============================================================================
template <bool GATHER>
__global__ __launch_bounds__(256)
void sgemm_kernel(const float* __restrict__ A, const int* __restrict__ ids, int lda,
                  const float* __restrict__ Bm, int ldb,
                  const float* __restrict__ bias,
                  float* __restrict__ C, int ldc, int coff,
                  int M, int N, int K)
{
    const int BM = 128, BN = 64, BK = 8;
    __shared__ float As[BK][BM];
    __shared__ float Bs[BK][BN];

    int nbn = N / BN;
    int bm = blockIdx.x / nbn;
    int bn = blockIdx.x % nbn;
    int tid = threadIdx.x;
    int tx = tid & 15;        // 0..15 -> 4 cols each
    int ty = tid >> 4;        // 0..15 -> 8 rows each

    float acc[8][4];
#pragma unroll
    for (int i = 0; i < 8; i++)
#pragma unroll
        for (int j = 0; j < 4; j++) acc[i][j] = 0.0f;

    // A-tile loader mapping: thread -> (row ar, 4 consecutive k at ak)
    int ar = tid >> 1;            // 0..127
    int ak = (tid & 1) * 4;       // 0 or 4
    int arow = bm * BM + ar;
    const float* arow_ptr;
    if (GATHER) arow_ptr = A + (size_t)ids[arow] * lda;
    else        arow_ptr = A + (size_t)arow * lda;

    // B-tile loader mapping: thread -> (k-row bk, 2 consecutive cols bc)
    int bkr = tid >> 5;           // 0..7
    int bc  = (tid & 31) * 2;     // 0..62
    const float* bptr = Bm + (size_t)bn * BN + bc;

    for (int k0 = 0; k0 < K; k0 += BK) {
        float4 av = make_float4(0.f, 0.f, 0.f, 0.f);
        if (k0 + ak < K) av = *(const float4*)(arow_ptr + k0 + ak);
        float2 bv = make_float2(0.f, 0.f);
        if (k0 + bkr < K) bv = *(const float2*)(bptr + (size_t)(k0 + bkr) * ldb);

        __syncthreads();
        As[ak + 0][ar] = av.x; As[ak + 1][ar] = av.y;
        As[ak + 2][ar] = av.z; As[ak + 3][ar] = av.w;
        Bs[bkr][bc] = bv.x; Bs[bkr][bc + 1] = bv.y;
        __syncthreads();

#pragma unroll
        for (int kk = 0; kk < BK; kk++) {
            float4 b4 = *(const float4*)&Bs[kk][tx * 4];
            float4 a0 = *(const float4*)&As[kk][ty * 8];
            float4 a1 = *(const float4*)&As[kk][ty * 8 + 4];
            float arr[8] = {a0.x, a0.y, a0.z, a0.w, a1.x, a1.y, a1.z, a1.w};
            float brr[4] = {b4.x, b4.y, b4.z, b4.w};
#pragma unroll
            for (int i = 0; i < 8; i++)
#pragma unroll
                for (int j = 0; j < 4; j++)
                    acc[i][j] += arr[i] * brr[j];
        }
    }

    float4 bb = *(const float4*)&bias[bn * BN + tx * 4];
    float bbr[4] = {bb.x, bb.y, bb.z, bb.w};
#pragma unroll
    for (int i = 0; i < 8; i++) {
        int row = bm * BM + ty * 8 + i;
        float4 o;
        o.x = acc[i][0] + bbr[0];
        o.y = acc[i][1] + bbr[1];
        o.z = acc[i][2] + bbr[2];
        o.w = acc[i][3] + bbr[3];
        *(float4*)(C + (size_t)row * ldc + coff + bn * BN + tx * 4) = o;
    }
}

// ============================================================================
// GRU recurrent scan, round 9: 4-way k-split + float4 weight loads + FFMA2.
// One block = 2 batch rows, 512 threads (16 warps):
//   k-quarter q = tid>>7 in {0..3} accumulates k in [64q, 64q+64)
//   gate phase: thread owns 4 gate columns  (LDG.128 per k-iter)
//   cand phase: thread owns 2 cand columns  (LDG.64  per k-iter)
// The two batch rows are packed as f32x2 so each MAC is one fma.rn.f32x2.
// Partials are combined via smem once per phase.
// Grid = 128 blocks: [0,64) = body stream, [64,128) = headline stream.
// ============================================================================
struct ScanArgs {
    const float* XG;    // [B*T, 768] x-projections (gates 0..511, cand 512..767)
    const float* Wgh;   // [256, 512] h-part of gate weights (k-major)
    const float* Wch;   // [256, 256] h-part of cand weights (k-major)
    const int*   ids;   // [B, T]
    float*       outs;  // [B*T, 256] or nullptr
    float*       hfin;  // g_hcat or nullptr
    int          hoff;  // column offset into g_hcat
    int          T;
};

__global__ __launch_bounds__(512)
void gru_scan_kernel(ScanArgs body, ScanArgs head)
{
    ScanArgs A = (blockIdx.x < 64) ? body : head;
    int bid = blockIdx.x & 63;
    int b0 = bid * 2;
    int b1 = b0 + 1;
    int tid = threadIdx.x;
    int q  = tid >> 7;            // k-quarter 0..3 (uniform per warp)
    int qt = tid & 127;           // thread-in-quarter
    int kq = q * 64;              // k range start

    __shared__ float2 sh_h2 [HID];          // (h_b0[k], h_b1[k])
    __shared__ float2 sh_rh2[HID];          // (r*h pairs)
    __shared__ float2 sh_u2 [HID];          // update-gate pairs
    __shared__ float2 sh_part [4][2 * HID]; // gate partials [quarter][col]   16KB
    __shared__ float2 sh_cpart[4][HID];     // cand partials [quarter][col]    8KB

    if (tid < HID) sh_h2[tid] = make_float2(0.f, 0.f);
    __syncthreads();

    const int T = A.T;
    const int c4 = qt * 4;        // gate columns owned
    const int c2 = qt * 2;        // cand columns owned

    const float* __restrict__ wg_base = A.Wgh + (size_t)kq * 512 + c4;
    const float* __restrict__ wc_base = A.Wch + (size_t)kq * 256 + c2;

    const unsigned long long* sh_h2u  = (const unsigned long long*)sh_h2;
    const unsigned long long* sh_rh2u = (const unsigned long long*)sh_rh2;

    for (int t = 0; t < T; t++) {
        const float* xg0 = A.XG + ((size_t)(b0 * T + t)) * 768;
        const float* xg1 = A.XG + ((size_t)(b1 * T + t)) * 768;

        // --- prefetch this step's x-parts + validity (hide DRAM latency) ---
        float xv0 = xg0[tid];              // gate x-part, col = tid (0..511)
        float xv1 = xg1[tid];
        float xc0 = 0.f, xc1 = 0.f;
        if (tid < HID) {
            xc0 = xg0[512 + tid];          // cand x-part
            xc1 = xg1[512 + tid];
        }
        bool v0 = (A.ids[b0 * T + t] != 0);
        bool v1 = (A.ids[b1 * T + t] != 0);

        // --- phase 1: gate partials, k in [kq,kq+64), cols c4..c4+3 ---
        {
            unsigned long long acc0 = 0ull, acc1 = 0ull, acc2 = 0ull, acc3 = 0ull;
#pragma unroll 16
            for (int kk = 0; kk < 64; kk++) {
                float4 w = *(const float4*)(wg_base + (size_t)kk * 512);
                unsigned long long h2 = sh_h2u[kq + kk];
                fma2(acc0, pack2(w.x), h2);
                fma2(acc1, pack2(w.y), h2);
                fma2(acc2, pack2(w.z), h2);
                fma2(acc3, pack2(w.w), h2);
            }
            unsigned long long* dst = (unsigned long long*)&sh_part[q][c4];
            dst[0] = acc0; dst[1] = acc1; dst[2] = acc2; dst[3] = acc3;
        }
        __syncthreads();

        // --- phase 2: combine quarters + sigmoid; col c = tid (512 cols) ---
        {
            int c = tid;
            float2 p0 = sh_part[0][c];
            float2 p1 = sh_part[1][c];
            float2 p2 = sh_part[2][c];
            float2 p3 = sh_part[3][c];
            float s0 = (p0.x + p1.x) + (p2.x + p3.x) + xv0;
            float s1 = (p0.y + p1.y) + (p2.y + p3.y) + xv1;
            float g0 = 1.f / (1.f + expf(-s0));
            float g1 = 1.f / (1.f + expf(-s1));
            if (c < HID) {                 // r gate -> r*h
                float2 h2 = sh_h2[c];
                sh_rh2[c] = make_float2(g0 * h2.x, g1 * h2.y);
            } else {                       // u gate
                sh_u2[c - HID] = make_float2(g0, g1);
            }
        }
        __syncthreads();

        // --- phase 3: cand partials, k in [kq,kq+64), cols c2..c2+1 ---
        {
            unsigned long long cacc0 = 0ull, cacc1 = 0ull;
#pragma unroll 16
            for (int kk = 0; kk < 64; kk++) {
                float2 w = *(const float2*)(wc_base + (size_t)kk * 256);
                unsigned long long rh = sh_rh2u[kq + kk];
                fma2(cacc0, pack2(w.x), rh);
                fma2(cacc1, pack2(w.y), rh);
            }
            unsigned long long* dst = (unsigned long long*)&sh_cpart[q][c2];
            dst[0] = cacc0; dst[1] = cacc1;
        }
        __syncthreads();

        // --- phase 4: combine + tanh + state update (threads < 256) ---
        if (tid < HID) {
            int c = tid;
            float2 p0 = sh_cpart[0][c];
            float2 p1 = sh_cpart[1][c];
            float2 p2 = sh_cpart[2][c];
            float2 p3 = sh_cpart[3][c];
            float cc0 = tanhf((p0.x + p1.x) + (p2.x + p3.x) + xc0);
            float cc1 = tanhf((p0.y + p1.y) + (p2.y + p3.y) + xc1);
            float2 u2 = sh_u2[c];
            float2 ho = sh_h2[c];
            float hn0 = u2.x * ho.x + (1.f - u2.x) * cc0;
            float hn1 = u2.y * ho.y + (1.f - u2.y) * cc1;
            if (A.outs) {
                A.outs[((size_t)(b0 * T + t)) * 256 + c] = v0 ? hn0 : 0.f;
                A.outs[((size_t)(b1 * T + t)) * 256 + c] = v1 ? hn1 : 0.f;
            }
            sh_h2[c] = make_float2(v0 ? hn0 : ho.x, v1 ? hn1 : ho.y);
        }
        __syncthreads();
    }

    if (A.hfin && tid < HID) {
        float2 h2 = sh_h2[tid];
        A.hfin[(size_t)b0 * 512 + A.hoff + tid] = h2.x;
        A.hfin[(size_t)b1 * 512 + A.hoff + tid] = h2.y;
    }
}

// ============================================================================
// Final projection: out[128,4] = [h_head | h_body] @ W_pred + b_pred
// ============================================================================
__global__ void final_pred_kernel(const float* __restrict__ Wp,
                                  const float* __restrict__ bp,
                                  float* __restrict__ out)
{
    int b = threadIdx.x;   // 0..127
    float a0 = bp[0], a1 = bp[1], a2 = bp[2], a3 = bp[3];
    const float* h = g_hcat + (size_t)b * 512;
#pragma unroll 8
    for (int j = 0; j < 512; j++) {
        float hv = h[j];
        float4 w = *(const float4*)(Wp + j * 4);
        a0 += hv * w.x; a1 += hv * w.y; a2 += hv * w.z; a3 += hv * w.w;
    }
    *(float4*)(out + b * 4) = make_float4(a0, a1, a2, a3);
}

// ============================================================================
// Launch: L0 x-GEMMs -> L0 scan -> L1 x-GEMMs -> L1 scan -> final projection
// ============================================================================
extern "C" void kernel_launch(void* const* d_in, const int* in_sizes, int n_in,
                              void* d_out, int out_size)
{
    (void)n_in; (void)out_size;

    // Fixed slots (same in both plausible metadata orders)
    const int*   ids_h  = (const int*)d_in[0];
    const int*   ids_b  = (const int*)d_in[1];
    const float* emb    = (const float*)d_in[2];

    // Detect metadata layout from element counts.
    const float *hd0_Wg, *hd0_bg, *hd0_Wc, *hd0_bc;
    const float *hd1_Wg, *hd1_bg, *hd1_Wc, *hd1_bc;
    const float *bd0_Wg, *bd0_bg, *bd0_Wc, *bd0_bc;
    const float *bd1_Wg, *bd1_bg, *bd1_Wc, *bd1_bc;
    const float *W_pred, *b_pred;

    if (in_sizes[3] == (2 * HID) * 4 && in_sizes[4] == 4) {
        // dict order
        W_pred = (const float*)d_in[3];
        b_pred = (const float*)d_in[4];
        hd0_Wg = (const float*)d_in[5];  hd0_bg = (const float*)d_in[6];
        hd0_Wc = (const float*)d_in[7];  hd0_bc = (const float*)d_in[8];
        hd1_Wg = (const float*)d_in[9];  hd1_bg = (const float*)d_in[10];
        hd1_Wc = (const float*)d_in[11]; hd1_bc = (const float*)d_in[12];
        bd0_Wg = (const float*)d_in[13]; bd0_bg = (const float*)d_in[14];
        bd0_Wc = (const float*)d_in[15]; bd0_bc = (const float*)d_in[16];
        bd1_Wg = (const float*)d_in[17]; bd1_bg = (const float*)d_in[18];
        bd1_Wc = (const float*)d_in[19]; bd1_bc = (const float*)d_in[20];
    } else {
        // signature order
        hd0_Wg = (const float*)d_in[3];  hd0_bg = (const float*)d_in[4];
        hd0_Wc = (const float*)d_in[5];  hd0_bc = (const float*)d_in[6];
        hd1_Wg = (const float*)d_in[7];  hd1_bg = (const float*)d_in[8];
        hd1_Wc = (const float*)d_in[9];  hd1_bc = (const float*)d_in[10];
        bd0_Wg = (const float*)d_in[11]; bd0_bg = (const float*)d_in[12];
        bd0_Wc = (const float*)d_in[13]; bd0_bc = (const float*)d_in[14];
        bd1_Wg = (const float*)d_in[15]; bd1_bg = (const float*)d_in[16];
        bd1_Wc = (const float*)d_in[17]; bd1_bc = (const float*)d_in[18];
        W_pred = (const float*)d_in[19];
        b_pred = (const float*)d_in[20];
    }

    float* out = (float*)d_out;

    float *XG_h, *XG_b, *out_h, *out_b, *hcat;
    cudaGetSymbolAddress((void**)&XG_h, g_XG_h);
    cudaGetSymbolAddress((void**)&XG_b, g_XG_b);
    cudaGetSymbolAddress((void**)&out_h, g_out_h);
    cudaGetSymbolAddress((void**)&out_b, g_out_b);
    cudaGetSymbolAddress((void**)&hcat, g_hcat);

    const int Mh = BATCH * T_H;   // 4096
    const int Mb = BATCH * T_B;   // 65536

    // ---- Layer-0 x-projections (embedding gather fused) ----
    sgemm_kernel<true><<<(Mh / 128) * (512 / 64), 256>>>(
        emb, ids_h, EMB, hd0_Wg, 512, hd0_bg, XG_h, 768, 0,   Mh, 512, EMB);
    sgemm_kernel<true><<<(Mh / 128) * (256 / 64), 256>>>(
        emb, ids_h, EMB, hd0_Wc, 256, hd0_bc, XG_h, 768, 512, Mh, 256, EMB);
    sgemm_kernel<true><<<(Mb / 128) * (512 / 64), 256>>>(
        emb, ids_b, EMB, bd0_Wg, 512, bd0_bg, XG_b, 768, 0,   Mb, 512, EMB);
    sgemm_kernel<true><<<(Mb / 128) * (256 / 64), 256>>>(
        emb, ids_b, EMB, bd0_Wc, 256, bd0_bc, XG_b, 768, 512, Mb, 256, EMB);

    // ---- Layer-0 scan (body + headline in one launch) ----
    {
        ScanArgs body = { XG_b, bd0_Wg + (size_t)EMB * 512, bd0_Wc + (size_t)EMB * 256,
                          ids_b, out_b, nullptr, 0, T_B };
        ScanArgs head = { XG_h, hd0_Wg + (size_t)EMB * 512, hd0_Wc + (size_t)EMB * 256,
                          ids_h, out_h, nullptr, 0, T_H };
        gru_scan_kernel<<<128, 512>>>(body, head);
    }

    // ---- Layer-1 x-projections (reuse XG buffers) ----
    sgemm_kernel<false><<<(Mh / 128) * (512 / 64), 256>>>(
        out_h, nullptr, HID, hd1_Wg, 512, hd1_bg, XG_h, 768, 0,   Mh, 512, HID);
    sgemm_kernel<false><<<(Mh / 128) * (256 / 64), 256>>>(
        out_h, nullptr, HID, hd1_Wc, 256, hd1_bc, XG_h, 768, 512, Mh, 256, HID);
    sgemm_kernel<false><<<(Mb / 128) * (512 / 64), 256>>>(
        out_b, nullptr, HID, bd1_Wg, 512, bd1_bg, XG_b, 768, 0,   Mb, 512, HID);
    sgemm_kernel<false><<<(Mb / 128) * (256 / 64), 256>>>(
        out_b, nullptr, HID, bd1_Wc, 256, bd1_bc, XG_b, 768, 512, Mb, 256, HID);

    // ---- Layer-1 scan -> final hidden states ----
    {
        ScanArgs body = { XG_b, bd1_Wg + (size_t)HID * 512, bd1_Wc + (size_t)HID * 256,
                          ids_b, nullptr, hcat, 256, T_B };
        ScanArgs head = { XG_h, hd1_Wg + (size_t)HID * 512, hd1_Wc + (size_t)HID * 256,
                          ids_h, nullptr, hcat, 0, T_H };
        gru_scan_kernel<<<128, 512>>>(body, head);
    }

    // ---- Final projection ----
    final_pred_kernel<<<1, 128>>>(W_pred, b_pred, out);
}